// round 9
// baseline (speedup 1.0000x reference)
#include <cuda_runtime.h>
#include <cstdint>

#define KDIM 64
#define MDIM 16
#define TPB  256
#define GRID 592                    // 148 SMs x 4 blocks
#define NWARPS (GRID * (TPB / 32))  // 4736
#define WPS  (NWARPS / 2)           // 2368 warps per side
#define KC   16                     // k per staged chunk (4 chunks per 32-row group)
#define TSTRIDE 20                  // floats per tile row (16 data + 4 pad)
#define BUFF (32 * TSTRIDE)         // 640 floats per buffer

typedef unsigned long long u64;
typedef unsigned int u32;

__device__ __forceinline__ u64 pack2(float lo, float hi) {
    u64 r;
    asm("mov.b64 %0, {%1, %2};" : "=l"(r) : "f"(lo), "f"(hi));
    return r;
}
__device__ __forceinline__ void unpack2(u64 v, float& lo, float& hi) {
    asm("mov.b64 {%0, %1}, %2;" : "=f"(lo), "=f"(hi) : "l"(v));
}
__device__ __forceinline__ u64 fma2(u64 a, u64 b, u64 c) {
    u64 d;
    asm("fma.rn.f32x2 %0, %1, %2, %3;" : "=l"(d) : "l"(a), "l"(b), "l"(c));
    return d;
}
__device__ __forceinline__ void cp16(u32 smem_dst, const void* gsrc) {
    asm volatile("cp.async.cg.shared.global [%0], [%1], 16;\n"
                 :: "r"(smem_dst), "l"(gsrc));
}
__device__ __forceinline__ void cp_commit() {
    asm volatile("cp.async.commit_group;\n");
}
template <int N>
__device__ __forceinline__ void cp_wait() {
    asm volatile("cp.async.wait_group %0;\n" :: "n"(N));
}

__global__ __launch_bounds__(TPB, 4)
void dual_compress_kernel(const float* __restrict__ phi_fwd,
                          const float* __restrict__ phi_bwd,
                          const float* __restrict__ alpha_fwd,
                          const float* __restrict__ alpha_bwd,
                          float* __restrict__ out,
                          int V)
{
    // Warp-private double buffers: 8 warps x 2 x 640 floats = 40,960 B
    __shared__ float tile[TPB / 32][2][BUFF];
    // Both sides' weight tables: wt[side*256 + k*4 + (2h|0..1)] -> 8,192 B
    __shared__ ulonglong2 wt[2 * KDIM * 4];
    u64* wtf = (u64*)wt;

    const int tid   = threadIdx.x;
    const int w     = tid >> 5;
    const int lane  = tid & 31;
    const int halfL = lane & 15;    // row-lane within chunk
    const int h     = lane >> 4;    // m-half: 0 -> m[0:8), 1 -> m[8:16)

    // ---- warp's contiguous row range on its side (near-perfect balance)
    const int gw   = blockIdx.x * (TPB / 32) + w;   // 0..4735
    const int side = gw & 1;
    const int wid  = gw >> 1;                        // 0..2367
    const float* __restrict__ phi = side ? phi_bwd : phi_fwd;
    float* __restrict__ y = out + (size_t)side * (size_t)V * MDIM;

    const int rlo   = (int)((long long)wid * V / WPS);
    const int rhi   = (int)((long long)(wid + 1) * V / WPS);
    const int nrc   = (rhi - rlo + 31) >> 5;         // 32-row groups
    const int nch   = nrc * 4;                       // staged chunks (KC=16)

    u32 tb0 = (u32)__cvta_generic_to_shared(&tile[w][0][0]);
    u32 tb1 = (u32)__cvta_generic_to_shared(&tile[w][1][0]);

    // stage chunk n into buffer n&1: rows [rlo + (n>>2)*32, +32), k [(n&3)*16, +16)
    auto stage = [&](int n) {
        const int rbase = rlo + (n >> 2) * 32;
        const int kc    = n & 3;
        const u32 tb    = (n & 1) ? tb1 : tb0;
        const float* src = phi + (size_t)kc * KC;
#pragma unroll
        for (int i = 0; i < 4; ++i) {                // 128 cp16 per warp
            int idx  = lane + 32 * i;
            int row  = idx >> 2;                     // 0..31
            int c4   = idx & 3;
            int grow = min(rbase + row, V - 1);
            cp16(tb + (u32)(row * TSTRIDE + c4 * 4) * 4u,
                 src + (size_t)grow * KDIM + c4 * 4);
        }
        cp_commit();
    };

    // ---- prologue: two chunks in flight before anything else
    stage(0);
    stage(1);

    // ---- build both weight tables while loads fly
#pragma unroll
    for (int t = 0; t < 4; ++t) {
        int idx = tid + t * TPB;                     // 0..1023
        int s   = idx >> 9;
        int rem = idx & 511;
        int k   = rem >> 3;
        int mp  = rem & 7;
        const float* __restrict__ alpha = s ? alpha_bwd : alpha_fwd;
        float w0 = __expf(alpha[(2 * mp)     * KDIM + k]);
        float w1 = __expf(alpha[(2 * mp + 1) * KDIM + k]);
        wtf[idx] = pack2(w0, w1);
    }
    __syncthreads();   // weights visible; the only CTA-wide barrier

    // this half's weight slice: index k*4 + {0,1}
    const ulonglong2* __restrict__ wk = &wt[side * KDIM * 4 + 2 * h];

    // accs: [row(2)][mp(4)] as f32x2 over m-pairs
    u64 acc[8];
#pragma unroll
    for (int q = 0; q < 8; ++q) acc[q] = 0ull;

    for (int n = 0; n < nch; ++n) {
        if (n == nch - 1) cp_wait<0>(); else cp_wait<1>();
        __syncwarp();

        const int buf = n & 1;
        const float* tb = &tile[w][buf][0];
        const float4* __restrict__ tA = (const float4*)(tb + halfL * TSTRIDE);
        const float4* __restrict__ tB = (const float4*)(tb + (halfL + 16) * TSTRIDE);

#pragma unroll
        for (int j4 = 0; j4 < KC / 4; ++j4) {        // 4 iters
            float4 a0 = tA[j4];
            float4 a1 = tB[j4];
            float e0[4], e1[4];
            e0[0] = __expf(a0.x); e0[1] = __expf(a0.y); e0[2] = __expf(a0.z); e0[3] = __expf(a0.w);
            e1[0] = __expf(a1.x); e1[1] = __expf(a1.y); e1[2] = __expf(a1.z); e1[3] = __expf(a1.w);

            const int kb = (n & 3) * KC + j4 * 4;
#pragma unroll
            for (int j = 0; j < 4; ++j) {
                const int k = kb + j;
                u64 E0 = pack2(e0[j], e0[j]);
                u64 E1 = pack2(e1[j], e1[j]);
                ulonglong2 wA = wk[k * 4];           // 2 m-pairs
                ulonglong2 wB = wk[k * 4 + 1];       // 2 m-pairs
                acc[0] = fma2(E0, wA.x, acc[0]);
                acc[1] = fma2(E0, wA.y, acc[1]);
                acc[2] = fma2(E0, wB.x, acc[2]);
                acc[3] = fma2(E0, wB.y, acc[3]);
                acc[4] = fma2(E1, wA.x, acc[4]);
                acc[5] = fma2(E1, wA.y, acc[5]);
                acc[6] = fma2(E1, wB.x, acc[6]);
                acc[7] = fma2(E1, wB.y, acc[7]);
            }
        }

        // prefetch chunk n+2 into the buffer just consumed
        if (n + 2 < nch) {
            __syncwarp();
            stage(n + 2);
        }

        // 32-row group complete: finalize + store + reset
        if ((n & 3) == 3) {
            const int rbase = rlo + (n >> 2) * 32;
            const int r0 = rbase + halfL;
            const int r1 = rbase + 16 + halfL;

            float ya[8], yb[8];
#pragma unroll
            for (int q = 0; q < 4; ++q) {
                float sa, sb;
                unpack2(acc[q], sa, sb);
                ya[2 * q] = __logf(sa); ya[2 * q + 1] = __logf(sb);
                unpack2(acc[4 + q], sa, sb);
                yb[2 * q] = __logf(sa); yb[2 * q + 1] = __logf(sb);
                acc[q] = 0ull; acc[4 + q] = 0ull;
            }
            if (r0 < rhi) {
                float4* o = (float4*)(y + (size_t)r0 * MDIM + 8 * h);
                o[0] = make_float4(ya[0], ya[1], ya[2], ya[3]);
                o[1] = make_float4(ya[4], ya[5], ya[6], ya[7]);
            }
            if (r1 < rhi) {
                float4* o = (float4*)(y + (size_t)r1 * MDIM + 8 * h);
                o[0] = make_float4(yb[0], yb[1], yb[2], yb[3]);
                o[1] = make_float4(yb[4], yb[5], yb[6], yb[7]);
            }
        }
    }
}

extern "C" void kernel_launch(void* const* d_in, const int* in_sizes, int n_in,
                              void* d_out, int out_size)
{
    const float* d_out_t   = (const float*)d_in[0];  // (V, 64) fwd phi
    const float* d_in_t    = (const float*)d_in[1];  // (V, 64) bwd phi
    const float* alpha_fwd = (const float*)d_in[2];  // (16, 64)
    const float* alpha_bwd = (const float*)d_in[3];  // (16, 64)
    float* out = (float*)d_out;                      // [y_fwd (V,16) | y_bwd (V,16)]

    const int V = in_sizes[0] / KDIM;

    dual_compress_kernel<<<GRID, TPB>>>(d_out_t, d_in_t, alpha_fwd, alpha_bwd, out, V);
}

// round 10
// speedup vs baseline: 1.3902x; 1.3902x over previous
#include <cuda_runtime.h>
#include <cstdint>

#define KDIM 64
#define MDIM 16
#define TPB  128
#define RPW  64                 // rows per warp (2 per lane)
#define RPB  (4 * RPW)          // 256 rows per block
#define KC   16                 // k per staged chunk
#define NCH  (KDIM / KC)        // 4 chunks
#define WSLICE (RPW * KC)       // 1024 floats per warp-buffer (no padding!)

typedef unsigned long long u64;
typedef unsigned int u32;

__device__ __forceinline__ u64 pack2(float lo, float hi) {
    u64 r;
    asm("mov.b64 %0, {%1, %2};" : "=l"(r) : "f"(lo), "f"(hi));
    return r;
}
__device__ __forceinline__ void unpack2(u64 v, float& lo, float& hi) {
    asm("mov.b64 {%0, %1}, %2;" : "=f"(lo), "=f"(hi) : "l"(v));
}
__device__ __forceinline__ u64 fma2(u64 a, u64 b, u64 c) {
    u64 d;
    asm("fma.rn.f32x2 %0, %1, %2, %3;" : "=l"(d) : "l"(a), "l"(b), "l"(c));
    return d;
}
__device__ __forceinline__ void cp16(u32 smem_dst, const void* gsrc) {
    asm volatile("cp.async.cg.shared.global [%0], [%1], 16;\n"
                 :: "r"(smem_dst), "l"(gsrc));
}
__device__ __forceinline__ void cp_commit() {
    asm volatile("cp.async.commit_group;\n");
}
template <int N>
__device__ __forceinline__ void cp_wait() {
    asm volatile("cp.async.wait_group %0;\n" :: "n"(N));
}

// rotation swizzle: float4 (row, c4) lives at slot (c4 + row + (row>>1)) & 3
__device__ __forceinline__ int rot4(int row, int c4) {
    return (c4 + row + (row >> 1)) & 3;
}

__global__ __launch_bounds__(TPB, 6)
void dual_compress_kernel(const float* __restrict__ phi_fwd,
                          const float* __restrict__ phi_bwd,
                          const float* __restrict__ alpha_fwd,
                          const float* __restrict__ alpha_bwd,
                          float* __restrict__ out,
                          int V)
{
    // Warp-private double buffers, unpadded + swizzled: 4 x 2 x 4096 B = 32 KB
    __shared__ float tile[4][2][WSLICE];
    // Single-side weight table: wt[k*4 + q] = m-pairs {2q, 2q+1}; 4 KB
    __shared__ ulonglong2 wt[KDIM * 4];
    u64* wtf = (u64*)wt;

    const int side = blockIdx.y;
    const float* __restrict__ phi   = side ? phi_bwd   : phi_fwd;
    const float* __restrict__ alpha = side ? alpha_bwd : alpha_fwd;
    float* __restrict__ y = out + (size_t)side * (size_t)V * MDIM;

    const int tid  = threadIdx.x;
    const int w    = tid >> 5;
    const int lane = tid & 31;

    const int blockRow = blockIdx.x * RPB;
    const int wbase    = blockRow + w * RPW;

    u32 tb0 = (u32)__cvta_generic_to_shared(&tile[w][0][0]);
    u32 tb1 = (u32)__cvta_generic_to_shared(&tile[w][1][0]);

    // stage chunk ch (k in [ch*16, ch*16+16)) of this warp's 64-row slab
    auto stage = [&](int ch) {
        const u32 tb = (ch & 1) ? tb1 : tb0;
        const float* src = phi + (size_t)ch * KC;
#pragma unroll
        for (int i = 0; i < 8; ++i) {                  // 256 float4 / 32 lanes
            int idx  = lane + 32 * i;
            int row  = idx >> 2;                        // 0..63
            int c4   = idx & 3;
            int grow = min(wbase + row, V - 1);
            int slot = row * 4 + rot4(row, c4);         // swizzled float4 slot
            cp16(tb + (u32)slot * 16u,
                 src + (size_t)grow * KDIM + c4 * 4);
        }
        cp_commit();
    };

    // ---- prologue: two chunks in flight
    stage(0);
    stage(1);

    // ---- weight table for this side while loads fly
#pragma unroll
    for (int t = 0; t < 4; ++t) {
        int idx = tid + t * TPB;                        // 0..511
        int k   = idx >> 3;
        int mp  = idx & 7;
        float w0 = __expf(alpha[(2 * mp)     * KDIM + k]);
        float w1 = __expf(alpha[(2 * mp + 1) * KDIM + k]);
        wtf[idx] = pack2(w0, w1);
    }
    __syncthreads();   // the only CTA-wide barrier

    const int r0 = wbase + lane;
    const int r1 = wbase + lane + 32;
    const int rb = (lane + (lane >> 1)) & 3;           // same rot for lane and lane+32

    u64 acc0[8], acc1[8];
#pragma unroll
    for (int q = 0; q < 8; ++q) { acc0[q] = 0ull; acc1[q] = 0ull; }

#pragma unroll
    for (int ch = 0; ch < NCH; ++ch) {
        if (ch == NCH - 1) cp_wait<0>(); else cp_wait<1>();
        __syncwarp();

        const int buf = ch & 1;
        const float4* __restrict__ t4 = (const float4*)&tile[w][buf][0];
        const int base0 = lane * 4;                     // row lane
        const int base1 = (lane + 32) * 4;              // row lane+32

#pragma unroll
        for (int j4 = 0; j4 < KC / 4; ++j4) {          // 4 iters
            const int s = (j4 + rb) & 3;
            float4 a0 = t4[base0 + s];
            float4 a1 = t4[base1 + s];

            float e0[4], e1[4];
            e0[0] = __expf(a0.x); e0[1] = __expf(a0.y); e0[2] = __expf(a0.z); e0[3] = __expf(a0.w);
            e1[0] = __expf(a1.x); e1[1] = __expf(a1.y); e1[2] = __expf(a1.z); e1[3] = __expf(a1.w);

            const int kb = ch * KC + j4 * 4;
#pragma unroll
            for (int j = 0; j < 4; ++j) {
                const int k = kb + j;
                u64 E0 = pack2(e0[j], e0[j]);
                u64 E1 = pack2(e1[j], e1[j]);
                ulonglong2 w01 = wt[k * 4 + 0];
                ulonglong2 w23 = wt[k * 4 + 1];
                ulonglong2 w45 = wt[k * 4 + 2];
                ulonglong2 w67 = wt[k * 4 + 3];
                acc0[0] = fma2(E0, w01.x, acc0[0]);
                acc1[0] = fma2(E1, w01.x, acc1[0]);
                acc0[1] = fma2(E0, w01.y, acc0[1]);
                acc1[1] = fma2(E1, w01.y, acc1[1]);
                acc0[2] = fma2(E0, w23.x, acc0[2]);
                acc1[2] = fma2(E1, w23.x, acc1[2]);
                acc0[3] = fma2(E0, w23.y, acc0[3]);
                acc1[3] = fma2(E1, w23.y, acc1[3]);
                acc0[4] = fma2(E0, w45.x, acc0[4]);
                acc1[4] = fma2(E1, w45.x, acc1[4]);
                acc0[5] = fma2(E0, w45.y, acc0[5]);
                acc1[5] = fma2(E1, w45.y, acc1[5]);
                acc0[6] = fma2(E0, w67.x, acc0[6]);
                acc1[6] = fma2(E1, w67.x, acc1[6]);
                acc0[7] = fma2(E0, w67.y, acc0[7]);
                acc1[7] = fma2(E1, w67.y, acc1[7]);
            }
        }

        // prefetch chunk ch+2 into the buffer just consumed
        if (ch + 2 < NCH) {
            __syncwarp();
            stage(ch + 2);
        }
    }

    // ---- epilogue: y = log(sum)
    float y0[MDIM], y1[MDIM];
#pragma unroll
    for (int q = 0; q < 8; ++q) {
        float sa, sb;
        unpack2(acc0[q], sa, sb);
        y0[2 * q] = __logf(sa); y0[2 * q + 1] = __logf(sb);
        unpack2(acc1[q], sa, sb);
        y1[2 * q] = __logf(sa); y1[2 * q + 1] = __logf(sb);
    }

    if (r0 < V) {
        float4* o = (float4*)(y + (size_t)r0 * MDIM);
        o[0] = make_float4(y0[0],  y0[1],  y0[2],  y0[3]);
        o[1] = make_float4(y0[4],  y0[5],  y0[6],  y0[7]);
        o[2] = make_float4(y0[8],  y0[9],  y0[10], y0[11]);
        o[3] = make_float4(y0[12], y0[13], y0[14], y0[15]);
    }
    if (r1 < V) {
        float4* o = (float4*)(y + (size_t)r1 * MDIM);
        o[0] = make_float4(y1[0],  y1[1],  y1[2],  y1[3]);
        o[1] = make_float4(y1[4],  y1[5],  y1[6],  y1[7]);
        o[2] = make_float4(y1[8],  y1[9],  y1[10], y1[11]);
        o[3] = make_float4(y1[12], y1[13], y1[14], y1[15]);
    }
}

extern "C" void kernel_launch(void* const* d_in, const int* in_sizes, int n_in,
                              void* d_out, int out_size)
{
    const float* d_out_t   = (const float*)d_in[0];  // (V, 64) fwd phi
    const float* d_in_t    = (const float*)d_in[1];  // (V, 64) bwd phi
    const float* alpha_fwd = (const float*)d_in[2];  // (16, 64)
    const float* alpha_bwd = (const float*)d_in[3];  // (16, 64)
    float* out = (float*)d_out;                      // [y_fwd (V,16) | y_bwd (V,16)]

    const int V = in_sizes[0] / KDIM;

    dim3 grid((V + RPB - 1) / RPB, 2);
    dual_compress_kernel<<<grid, TPB>>>(d_out_t, d_in_t, alpha_fwd, alpha_bwd, out, V);
}